// round 12
// baseline (speedup 1.0000x reference)
#include <cuda_runtime.h>
#include <cuda_fp16.h>
#include <cstdint>

// ---------------------------------------------------------------------------
// PoetryGPT forward: fp16 HMMA GEMMs (fp16 weight arena, 3-stage cp.async,
// BM=128 and BM=64 variants) + fused flash attention.
// B=2,T=1024,D=1024,H=16,HD=64,L=8,V=32000,DF=4096
// ---------------------------------------------------------------------------

namespace {
constexpr int BATCH = 2;
constexpr int T     = 1024;
constexpr int D     = 1024;
constexpr int H     = 16;
constexpr int HD    = 64;
constexpr int NL    = 8;
constexpr int VOCAB = 32000;
constexpr int DF    = 4096;
constexpr int MROWS = BATCH * T;      // 2048

// fp16 weight arena, tensor-major, all [K,N] row-major
constexpr size_t QKV_L   = (size_t)D * 3 * D;
constexpr size_t OFF_QKV = 0;
constexpr size_t OFF_PROJ = (size_t)NL * QKV_L;
constexpr size_t OFF_W1   = OFF_PROJ + (size_t)NL * D * D;
constexpr size_t OFF_W2   = OFF_W1 + (size_t)NL * D * DF;
constexpr size_t OFF_LM   = OFF_W2 + (size_t)NL * DF * D;
constexpr size_t W_TOTAL  = OFF_LM + (size_t)D * VOCAB;

// GEMM smem geometry (3-stage)
constexpr int SA_STRIDE = 40;
constexpr int SB_STRIDE = 136;
constexpr int SB_STAGE  = 32 * SB_STRIDE;              // 4352 halfs
constexpr int SA_STAGE_128 = 128 * SA_STRIDE;          // 5120
constexpr int SA_STAGE_64  = 64 * SA_STRIDE;           // 2560
constexpr int GEMM_SMEM_128 = (3 * SA_STAGE_128 + 3 * SB_STAGE) * 2;  // 56832
constexpr int GEMM_SMEM_64  = (3 * SA_STAGE_64  + 3 * SB_STAGE) * 2;  // 41472
}

// Scratch (static device globals; no allocation anywhere)
__device__ float  g_h    [MROWS * D];
__device__ __half g_a16  [(size_t)MROWS * D];
__device__ __half g_qkv16[(size_t)MROWS * 3 * D];
__device__ __half g_f16  [(size_t)MROWS * DF];
__device__ __half g_o16  [(size_t)MROWS * D];
__device__ __half g_w16  [W_TOTAL];

// ---------------------------------------------------------------------------
__device__ __forceinline__ uint32_t smem_u32(const void* p) {
    uint32_t a;
    asm("{ .reg .u64 t; cvta.to.shared.u64 t, %1; cvt.u32.u64 %0, t; }"
        : "=r"(a) : "l"(p));
    return a;
}
#define CP_ASYNC16(sa, gp) \
    asm volatile("cp.async.cg.shared.global [%0], [%1], 16;" :: "r"(sa), "l"(gp))
#define CP_COMMIT() asm volatile("cp.async.commit_group;" ::: "memory")

__device__ __forceinline__ void ldmatrix_x4(uint32_t& r0, uint32_t& r1,
                                            uint32_t& r2, uint32_t& r3,
                                            uint32_t addr) {
    asm volatile("ldmatrix.sync.aligned.m8n8.x4.shared.b16 {%0,%1,%2,%3}, [%4];"
                 : "=r"(r0), "=r"(r1), "=r"(r2), "=r"(r3) : "r"(addr));
}
__device__ __forceinline__ void ldmatrix_x4_trans(uint32_t& r0, uint32_t& r1,
                                                  uint32_t& r2, uint32_t& r3,
                                                  uint32_t addr) {
    asm volatile("ldmatrix.sync.aligned.m8n8.x4.trans.shared.b16 {%0,%1,%2,%3}, [%4];"
                 : "=r"(r0), "=r"(r1), "=r"(r2), "=r"(r3) : "r"(addr));
}
__device__ __forceinline__ void mma16816(float* c, const uint32_t* a,
                                         const uint32_t* b) {
    asm volatile(
        "mma.sync.aligned.m16n8k16.row.col.f32.f16.f16.f32 "
        "{%0,%1,%2,%3}, {%4,%5,%6,%7}, {%8,%9}, {%0,%1,%2,%3};"
        : "+f"(c[0]), "+f"(c[1]), "+f"(c[2]), "+f"(c[3])
        : "r"(a[0]), "r"(a[1]), "r"(a[2]), "r"(a[3]), "r"(b[0]), "r"(b[1]));
}
__device__ __forceinline__ uint32_t h2pack(float x, float y) {
    __half2 h = __floats2half2_rn(x, y);
    return *(uint32_t*)&h;
}

// ---------------------------------------------------------------------------
// Block reductions (blockDim.x == 256)
// ---------------------------------------------------------------------------
__device__ __forceinline__ float blk_sum(float v) {
    __shared__ float sm[8];
    int lane = threadIdx.x & 31, w = threadIdx.x >> 5;
    #pragma unroll
    for (int o = 16; o; o >>= 1) v += __shfl_xor_sync(0xffffffffu, v, o);
    if (lane == 0) sm[w] = v;
    __syncthreads();
    if (w == 0) {
        float x = (lane < 8) ? sm[lane] : 0.f;
        #pragma unroll
        for (int o = 4; o; o >>= 1) x += __shfl_xor_sync(0xffffffffu, x, o);
        if (lane == 0) sm[0] = x;
    }
    __syncthreads();
    float r = sm[0];
    __syncthreads();
    return r;
}

// ---------------------------------------------------------------------------
// Weight conversion fp32 -> fp16 (elementwise, layout preserved)
// ---------------------------------------------------------------------------
__global__ void conv_w_kernel(const float* __restrict__ src, __half* __restrict__ dst) {
    size_t i = ((size_t)blockIdx.x * 256 + threadIdx.x) * 8;
    float4 v0 = *(const float4*)(src + i);
    float4 v1 = *(const float4*)(src + i + 4);
    uint2 p0, p1;
    p0.x = h2pack(v0.x, v0.y); p0.y = h2pack(v0.z, v0.w);
    p1.x = h2pack(v1.x, v1.y); p1.y = h2pack(v1.z, v1.w);
    *(uint2*)(dst + i)     = p0;
    *(uint2*)(dst + i + 4) = p1;
}

// ---------------------------------------------------------------------------
// QKV remap + convert: (L,H,D,HD)x3 fp32 -> arena [L][K=D][N=3D] fp16
// ---------------------------------------------------------------------------
__global__ void conv_qkv_kernel(const float* __restrict__ Wq,
                                const float* __restrict__ Wk,
                                const float* __restrict__ Wv,
                                __half* __restrict__ dst) {
    size_t i = ((size_t)blockIdx.x * 256 + threadIdx.x) * 4;
    int l = (int)(i / QKV_L);
    size_t rem = i % QKV_L;
    int k = (int)(rem / (3 * D));
    int col = (int)(rem % (3 * D));
    int s = col >> 10, nloc = col & 1023;
    int h = nloc >> 6, e = nloc & 63;
    const float* base = (s == 0) ? Wq : ((s == 1) ? Wk : Wv);
    const float* src = base + (size_t)l * H * D * HD + ((size_t)h * D + k) * HD + e;
    float4 v = *(const float4*)src;
    uint2 p;
    p.x = h2pack(v.x, v.y);
    p.y = h2pack(v.z, v.w);
    *(uint2*)(dst + i) = p;
}

// ---------------------------------------------------------------------------
// Embedding
// ---------------------------------------------------------------------------
__global__ void embed_kernel(const int* __restrict__ x,
                             const float* __restrict__ tok,
                             const float* __restrict__ pos,
                             float* __restrict__ out) {
    int row = blockIdx.x;
    int t   = row & (T - 1);
    int id  = x[row];
    int c   = threadIdx.x * 4;
    float4 a = *(const float4*)(tok + (size_t)id * D + c);
    float4 p = *(const float4*)(pos + (size_t)t * D + c);
    float4 r; r.x = a.x + p.x; r.y = a.y + p.y; r.z = a.z + p.z; r.w = a.w + p.w;
    *(float4*)(out + (size_t)row * D + c) = r;
}

// ---------------------------------------------------------------------------
// LayerNorm over D=1024, fp32 in -> fp16 out
// ---------------------------------------------------------------------------
__global__ void layernorm_kernel(const float* __restrict__ x,
                                 const float* __restrict__ g,
                                 const float* __restrict__ b,
                                 __half* __restrict__ y) {
    int row = blockIdx.x;
    int c   = threadIdx.x * 4;
    float4 v = *(const float4*)(x + (size_t)row * D + c);
    float mean = blk_sum(v.x + v.y + v.z + v.w) * (1.f / D);
    float dx = v.x - mean, dy = v.y - mean, dz = v.z - mean, dw = v.w - mean;
    float var = blk_sum(dx * dx + dy * dy + dz * dz + dw * dw) * (1.f / D);
    float inv = rsqrtf(var + 1e-5f);
    float4 gv = *(const float4*)(g + c);
    float4 bv = *(const float4*)(b + c);
    __half2* o = (__half2*)(y + (size_t)row * D + c);
    o[0] = __floats2half2_rn(dx * inv * gv.x + bv.x, dy * inv * gv.y + bv.y);
    o[1] = __floats2half2_rn(dz * inv * gv.z + bv.z, dw * inv * gv.w + bv.w);
}

// ---------------------------------------------------------------------------
// Shared GEMM epilogue (per warp-tile write)
// ---------------------------------------------------------------------------
__device__ __forceinline__ void gemm_epilogue(
    float acc[2][8][4], size_t m0, size_t n0, int wm, int wn, int lane,
    const float* bias, const float* res, float* Cf, __half* Ch,
    int N, int relu) {
    int rg = lane >> 2, cg = (lane & 3) * 2;
    #pragma unroll
    for (int mt = 0; mt < 2; mt++) {
        #pragma unroll
        for (int half = 0; half < 2; half++) {
            size_t r = m0 + wm * 32 + mt * 16 + rg + half * 8;
            #pragma unroll
            for (int nt = 0; nt < 8; nt++) {
                size_t c = n0 + wn * 64 + nt * 8 + cg;
                float vx = acc[mt][nt][half * 2 + 0];
                float vy = acc[mt][nt][half * 2 + 1];
                if (bias) { vx += bias[c]; vy += bias[c + 1]; }
                if (res) {
                    float2 rv = *(const float2*)(res + r * N + c);
                    vx += rv.x; vy += rv.y;
                }
                if (relu) { vx = fmaxf(vx, 0.f); vy = fmaxf(vy, 0.f); }
                if (Ch) {
                    *(__half2*)(Ch + r * N + c) = __floats2half2_rn(vx, vy);
                } else {
                    float2 v; v.x = vx; v.y = vy;
                    *(float2*)(Cf + r * N + c) = v;
                }
            }
        }
    }
}

// ---------------------------------------------------------------------------
// Shared GEMM mainloop compute (warp tile 32x64: 2 a-frags x 8 b-frags)
// ---------------------------------------------------------------------------
__device__ __forceinline__ void gemm_compute_tile(
    float acc[2][8][4], const __half* bufA, const __half* bufB,
    int wm, int wn, int lane) {
    #pragma unroll
    for (int ks = 0; ks < 2; ks++) {
        uint32_t a[2][4], b[8][2];
        #pragma unroll
        for (int mt = 0; mt < 2; mt++) {
            uint32_t ad = smem_u32(
                bufA + (wm * 32 + mt * 16 + (lane & 15)) * SA_STRIDE +
                ks * 16 + (lane >> 4) * 8);
            ldmatrix_x4(a[mt][0], a[mt][1], a[mt][2], a[mt][3], ad);
        }
        #pragma unroll
        for (int j2 = 0; j2 < 4; j2++) {
            uint32_t r0, r1, r2, r3;
            uint32_t bd = smem_u32(
                bufB + (ks * 16 + (lane & 15)) * SB_STRIDE +
                wn * 64 + j2 * 16 + (lane >> 4) * 8);
            ldmatrix_x4_trans(r0, r1, r2, r3, bd);
            b[j2 * 2][0] = r0; b[j2 * 2][1] = r1;
            b[j2 * 2 + 1][0] = r2; b[j2 * 2 + 1][1] = r3;
        }
        #pragma unroll
        for (int mt = 0; mt < 2; mt++)
            #pragma unroll
            for (int nt = 0; nt < 8; nt++)
                mma16816(acc[mt][nt], a[mt], b[nt]);
    }
}

// ---------------------------------------------------------------------------
// HMMA GEMM, BM=128: 256 threads (8 warps 4x2), 3-stage cp.async
// ---------------------------------------------------------------------------
__global__ void __launch_bounds__(256, 2)
gemm128_kernel(const __half* __restrict__ A, const __half* __restrict__ B,
               const float* __restrict__ bias, const float* res,
               float* __restrict__ Cf, __half* __restrict__ Ch,
               int N, int K, int relu) {
    extern __shared__ __half smem[];
    __half* sA = smem;
    __half* sB = smem + 3 * SA_STAGE_128;

    int tid = threadIdx.x, lane = tid & 31, wid = tid >> 5;
    int wm = wid & 3, wn = wid >> 2;
    size_t m0 = (size_t)blockIdx.y * 128, n0 = (size_t)blockIdx.x * 128;

    int lr  = tid >> 2;
    int seg = (tid & 3) * 8;
    const __half* Ag0 = A + (m0 + lr) * (size_t)K + seg;
    const __half* Ag1 = A + (m0 + lr + 64) * (size_t)K + seg;
    uint32_t saw0 = smem_u32(sA + lr * SA_STRIDE + seg);
    uint32_t saw1 = smem_u32(sA + (lr + 64) * SA_STRIDE + seg);

    int brow = tid >> 4;
    int bcol = (tid & 15) * 8;
    const __half* Bg = B + (size_t)brow * N + n0 + bcol;
    uint32_t sbw0 = smem_u32(sB + brow * SB_STRIDE + bcol);
    uint32_t sbw1 = smem_u32(sB + (brow + 16) * SB_STRIDE + bcol);

    int nk = K >> 5;
    auto issue = [&](int kb) {
        uint32_t ao = (uint32_t)((kb % 3) * SA_STAGE_128 * 2);
        uint32_t bo = (uint32_t)((kb % 3) * SB_STAGE * 2);
        size_t ga = (size_t)kb * 32;
        CP_ASYNC16(saw0 + ao, Ag0 + ga);
        CP_ASYNC16(saw1 + ao, Ag1 + ga);
        const __half* bg = Bg + (size_t)kb * 32 * N;
        CP_ASYNC16(sbw0 + bo, bg);
        CP_ASYNC16(sbw1 + bo, bg + (size_t)16 * N);
        CP_COMMIT();
    };

    float acc[2][8][4] = {};
    issue(0);
    issue(1);

    for (int kb = 0; kb < nk; kb++) {
        if (kb + 1 < nk) {
            asm volatile("cp.async.wait_group 1;" ::: "memory");
        } else {
            asm volatile("cp.async.wait_group 0;" ::: "memory");
        }
        __syncthreads();
        if (kb + 2 < nk) issue(kb + 2);
        gemm_compute_tile(acc, sA + (kb % 3) * SA_STAGE_128,
                          sB + (kb % 3) * SB_STAGE, wm, wn, lane);
    }
    gemm_epilogue(acc, m0, n0, wm, wn, lane, bias, res, Cf, Ch, N, relu);
}

// ---------------------------------------------------------------------------
// HMMA GEMM, BM=64: 128 threads (4 warps 2x2), 3-stage cp.async, 4 CTAs/SM
// ---------------------------------------------------------------------------
__global__ void __launch_bounds__(128, 4)
gemm64_kernel(const __half* __restrict__ A, const __half* __restrict__ B,
              const float* __restrict__ bias, const float* res,
              float* __restrict__ Cf, __half* __restrict__ Ch,
              int N, int K, int relu) {
    extern __shared__ __half smem[];
    __half* sA = smem;
    __half* sB = smem + 3 * SA_STAGE_64;

    int tid = threadIdx.x, lane = tid & 31, wid = tid >> 5;
    int wm = wid & 1, wn = wid >> 1;
    size_t m0 = (size_t)blockIdx.y * 64, n0 = (size_t)blockIdx.x * 128;

    // A: 64x32 halfs/stage = 256 chunks, 2/thread: c = tid + i*128
    int ar0 = tid >> 2,             as0 = (tid & 3) * 8;
    int ar1 = (tid + 128) >> 2,     as1 = ((tid + 128) & 3) * 8;
    const __half* Ag0 = A + (m0 + ar0) * (size_t)K + as0;
    const __half* Ag1 = A + (m0 + ar1) * (size_t)K + as1;
    uint32_t saw0 = smem_u32(sA + ar0 * SA_STRIDE + as0);
    uint32_t saw1 = smem_u32(sA + ar1 * SA_STRIDE + as1);

    // B: 32x128 halfs/stage = 512 chunks, 4/thread: c = tid + i*128
    int br[4], bc[4];
    uint32_t sbw[4];
    #pragma unroll
    for (int i = 0; i < 4; i++) {
        int c = tid + i * 128;
        br[i] = c >> 4;
        bc[i] = (c & 15) * 8;
        sbw[i] = smem_u32(sB + br[i] * SB_STRIDE + bc[i]);
    }

    int nk = K >> 5;
    auto issue = [&](int kb) {
        uint32_t ao = (uint32_t)((kb % 3) * SA_STAGE_64 * 2);
        uint32_t bo = (uint32_t)((kb % 3) * SB_STAGE * 2);
        size_t ga = (size_t)kb * 32;
        CP_ASYNC16(saw0 + ao, Ag0 + ga);
        CP_ASYNC16(saw1 + ao, Ag1 + ga);
        #pragma unroll
        for (int i = 0; i < 4; i++) {
            const __half* bg = B + (size_t)(kb * 32 + br[i]) * N + n0 + bc[i];
            CP_ASYNC16(sbw[i] + bo, bg);
        }
        CP_COMMIT();
    };

    float acc[2][8][4] = {};
    issue(0);
    issue(1);

    for (int kb = 0; kb < nk; kb++) {
        if (kb + 1 < nk) {
            asm volatile("cp.async.wait_group 1;" ::: "memory");
        } else {
            asm volatile("cp.async.wait_group 0;" ::: "memory");
        }
        __syncthreads();
        if (kb + 2 < nk) issue(kb + 2);
        gemm_compute_tile(acc, sA + (kb % 3) * SA_STAGE_64,
                          sB + (kb % 3) * SB_STAGE, wm, wn, lane);
    }
    gemm_epilogue(acc, m0, n0, wm, wn, lane, bias, res, Cf, Ch, N, relu);
}

// ---------------------------------------------------------------------------
// Fused causal flash attention (fp16 HMMA, fp32 online softmax)
// ---------------------------------------------------------------------------
__global__ void __launch_bounds__(128)
flash_attn_kernel(const __half* __restrict__ qkv, __half* __restrict__ o16) {
    constexpr int RS = 3 * D;
    constexpr int ST = 72;
    __shared__ __half sQ[64 * ST];
    __shared__ __half sK[2][64 * ST];
    __shared__ __half sV[2][64 * ST];

    int tid = threadIdx.x, lane = tid & 31, wid = tid >> 5;
    int bh = blockIdx.y;
    int b = bh >> 4, h = bh & 15;
    int tt = gridDim.x - 1 - blockIdx.x;
    int t0 = tt * 64;

    const __half* qb = qkv + (size_t)(b * T) * RS + h * HD;
    const __half* kb = qb + D;
    const __half* vb = qb + 2 * D;

    int seg = (tid & 7) * 8, rr = tid >> 3;
    #pragma unroll
    for (int i = 0; i < 4; i++) {
        int row = rr + i * 16;
        *(uint4*)&sQ[row * ST + seg] =
            *(const uint4*)(qb + (size_t)(t0 + row) * RS + seg);
    }
    __syncthreads();

    uint32_t qa[4][4];
    {
        int qr = wid * 16 + (lane & 15);
        #pragma unroll
        for (int kk = 0; kk < 4; kk++) {
            uint32_t ad = smem_u32(&sQ[qr * ST + kk * 16 + (lane >> 4) * 8]);
            ldmatrix_x4(qa[kk][0], qa[kk][1], qa[kk][2], qa[kk][3], ad);
        }
    }

    float m[2] = {-1e30f, -1e30f}, l[2] = {0.f, 0.f};
    float oacc[8][4] = {};
    int nst = tt + 1;

    {
        #pragma unroll
        for (int i = 0; i < 4; i++) {
            int row = rr + i * 16;
            CP_ASYNC16(smem_u32(&sK[0][row * ST + seg]), kb + (size_t)row * RS + seg);
            CP_ASYNC16(smem_u32(&sV[0][row * ST + seg]), vb + (size_t)row * RS + seg);
        }
        CP_COMMIT();
    }

    const float scale = 0.03125f;
    int trow0 = t0 + wid * 16 + (lane >> 2);

    for (int st = 0; st < nst; st++) {
        int buf = st & 1;
        asm volatile("cp.async.wait_group 0;" ::: "memory");
        __syncthreads();
        if (st + 1 < nst) {
            int nb = buf ^ 1;
            #pragma unroll
            for (int i = 0; i < 4; i++) {
                int row = rr + i * 16;
                const __half* kg = kb + (size_t)((st + 1) * 64 + row) * RS + seg;
                const __half* vg = vb + (size_t)((st + 1) * 64 + row) * RS + seg;
                CP_ASYNC16(smem_u32(&sK[nb][row * ST + seg]), kg);
                CP_ASYNC16(smem_u32(&sV[nb][row * ST + seg]), vg);
            }
            CP_COMMIT();
        }

        float sacc[8][4] = {};
        #pragma unroll
        for (int kk = 0; kk < 4; kk++) {
            uint32_t bfr[8][2];
            #pragma unroll
            for (int j2 = 0; j2 < 4; j2++) {
                uint32_t r0, r1, r2, r3;
                uint32_t ad = smem_u32(
                    &sK[buf][(j2 * 16 + (lane & 15)) * ST + kk * 16 + (lane >> 4) * 8]);
                ldmatrix_x4(r0, r1, r2, r3, ad);
                bfr[j2 * 2][0] = r0; bfr[j2 * 2][1] = r2;
                bfr[j2 * 2 + 1][0] = r1; bfr[j2 * 2 + 1][1] = r3;
            }
            #pragma unroll
            for (int j = 0; j < 8; j++)
                mma16816(sacc[j], qa[kk], bfr[j]);
        }

        bool diag = (st == tt);
        #pragma unroll
        for (int j = 0; j < 8; j++) {
            #pragma unroll
            for (int q = 0; q < 4; q++) {
                float v = sacc[j][q] * scale;
                if (diag) {
                    int s = st * 64 + j * 8 + (lane & 3) * 2 + (q & 1);
                    int t = trow0 + ((q < 2) ? 0 : 8);
                    if (s > t) v = -1e30f;
                }
                sacc[j][q] = v;
            }
        }

        float mx0 = -1e30f, mx1 = -1e30f;
        #pragma unroll
        for (int j = 0; j < 8; j++) {
            mx0 = fmaxf(mx0, fmaxf(sacc[j][0], sacc[j][1]));
            mx1 = fmaxf(mx1, fmaxf(sacc[j][2], sacc[j][3]));
        }
        #pragma unroll
        for (int o = 1; o <= 2; o <<= 1) {
            mx0 = fmaxf(mx0, __shfl_xor_sync(0xffffffffu, mx0, o));
            mx1 = fmaxf(mx1, __shfl_xor_sync(0xffffffffu, mx1, o));
        }
        float mn0 = fmaxf(m[0], mx0), mn1 = fmaxf(m[1], mx1);
        float a0 = __expf(m[0] - mn0), a1 = __expf(m[1] - mn1);
        m[0] = mn0; m[1] = mn1;

        float s0 = 0.f, s1 = 0.f;
        #pragma unroll
        for (int j = 0; j < 8; j++) {
            sacc[j][0] = __expf(sacc[j][0] - mn0);
            sacc[j][1] = __expf(sacc[j][1] - mn0);
            sacc[j][2] = __expf(sacc[j][2] - mn1);
            sacc[j][3] = __expf(sacc[j][3] - mn1);
            s0 += sacc[j][0] + sacc[j][1];
            s1 += sacc[j][2] + sacc[j][3];
        }
        #pragma unroll
        for (int o = 1; o <= 2; o <<= 1) {
            s0 += __shfl_xor_sync(0xffffffffu, s0, o);
            s1 += __shfl_xor_sync(0xffffffffu, s1, o);
        }
        l[0] = l[0] * a0 + s0;
        l[1] = l[1] * a1 + s1;
        #pragma unroll
        for (int j = 0; j < 8; j++) {
            oacc[j][0] *= a0; oacc[j][1] *= a0;
            oacc[j][2] *= a1; oacc[j][3] *= a1;
        }

        #pragma unroll
        for (int kk = 0; kk < 4; kk++) {
            uint32_t pa[4];
            pa[0] = h2pack(sacc[2 * kk][0], sacc[2 * kk][1]);
            pa[1] = h2pack(sacc[2 * kk][2], sacc[2 * kk][3]);
            pa[2] = h2pack(sacc[2 * kk + 1][0], sacc[2 * kk + 1][1]);
            pa[3] = h2pack(sacc[2 * kk + 1][2], sacc[2 * kk + 1][3]);
            uint32_t vfr[8][2];
            #pragma unroll
            for (int j2 = 0; j2 < 4; j2++) {
                uint32_t r0, r1, r2, r3;
                uint32_t ad = smem_u32(
                    &sV[buf][(kk * 16 + (lane & 15)) * ST + j2 * 16 + (lane >> 4) * 8]);
                ldmatrix_x4_trans(r0, r1, r2, r3, ad);
                vfr[j2 * 2][0] = r0; vfr[j2 * 2][1] = r1;
                vfr[j2 * 2 + 1][0] = r2; vfr[j2 * 2 + 1][1] = r3;
            }
            #pragma unroll
            for (int j = 0; j < 8; j++)
                mma16816(oacc[j], pa, vfr[j]);
        }
    }

    float inv0 = 1.f / l[0], inv1 = 1.f / l[1];
    int cg = (lane & 3) * 2;
    #pragma unroll
    for (int j = 0; j < 8; j++) {
        size_t r0 = (size_t)(b * T + trow0);
        size_t r1 = r0 + 8;
        int c = h * HD + j * 8 + cg;
        *(__half2*)(o16 + r0 * D + c) = __floats2half2_rn(oacc[j][0] * inv0, oacc[j][1] * inv0);
        *(__half2*)(o16 + r1 * D + c) = __floats2half2_rn(oacc[j][2] * inv1, oacc[j][3] * inv1);
    }
}

// ---------------------------------------------------------------------------
// Host orchestration
// ---------------------------------------------------------------------------
extern "C" void kernel_launch(void* const* d_in, const int* in_sizes, int n_in,
                              void* d_out, int out_size) {
    (void)in_sizes; (void)n_in; (void)out_size;
    const int*   x      = (const int*)  d_in[0];
    const float* tok    = (const float*)d_in[1];
    const float* pos    = (const float*)d_in[2];
    const float* Wq     = (const float*)d_in[3];
    const float* Wk     = (const float*)d_in[4];
    const float* Wv     = (const float*)d_in[5];
    const float* Wproj  = (const float*)d_in[6];
    const float* bproj  = (const float*)d_in[7];
    const float* ln1_g  = (const float*)d_in[8];
    const float* ln1_b  = (const float*)d_in[9];
    const float* ln2_g  = (const float*)d_in[10];
    const float* ln2_b  = (const float*)d_in[11];
    const float* W1     = (const float*)d_in[12];
    const float* b1     = (const float*)d_in[13];
    const float* W2     = (const float*)d_in[14];
    const float* b2     = (const float*)d_in[15];
    const float* lnf_g  = (const float*)d_in[16];
    const float* lnf_b  = (const float*)d_in[17];
    const float* Wlm    = (const float*)d_in[18];
    const float* blm    = (const float*)d_in[19];
    float* out = (float*)d_out;

    float *h_;
    __half *a16, *qkv16, *f16, *o16, *w16;
    cudaGetSymbolAddress((void**)&h_,    g_h);
    cudaGetSymbolAddress((void**)&a16,   g_a16);
    cudaGetSymbolAddress((void**)&qkv16, g_qkv16);
    cudaGetSymbolAddress((void**)&f16,   g_f16);
    cudaGetSymbolAddress((void**)&o16,   g_o16);
    cudaGetSymbolAddress((void**)&w16,   g_w16);

    static int smem_set = 0;
    if (!smem_set) {
        cudaFuncSetAttribute(gemm128_kernel,
                             cudaFuncAttributeMaxDynamicSharedMemorySize, GEMM_SMEM_128);
        cudaFuncSetAttribute(gemm64_kernel,
                             cudaFuncAttributeMaxDynamicSharedMemorySize, GEMM_SMEM_64);
        smem_set = 1;
    }

    // ---- weight conversion fp32 -> fp16 arena (5 launches) ----
    conv_qkv_kernel<<<(unsigned)(NL * QKV_L / 1024), 256>>>(Wq, Wk, Wv, w16 + OFF_QKV);
    conv_w_kernel<<<(unsigned)((size_t)NL * D * D / 2048), 256>>>(Wproj, w16 + OFF_PROJ);
    conv_w_kernel<<<(unsigned)((size_t)NL * D * DF / 2048), 256>>>(W1, w16 + OFF_W1);
    conv_w_kernel<<<(unsigned)((size_t)NL * DF * D / 2048), 256>>>(W2, w16 + OFF_W2);
    conv_w_kernel<<<(unsigned)((size_t)D * VOCAB / 2048), 256>>>(Wlm, w16 + OFF_LM);

    embed_kernel<<<MROWS, 256>>>(x, tok, pos, h_);

    for (int l = 0; l < NL; l++) {
        layernorm_kernel<<<MROWS, 256>>>(h_, ln1_g + l * D, ln1_b + l * D, a16);

        // fused QKV GEMM (384 CTAs, BM=128)
        gemm128_kernel<<<dim3(3 * D / 128, MROWS / 128), 256, GEMM_SMEM_128>>>(
            a16, w16 + OFF_QKV + (size_t)l * QKV_L,
            nullptr, nullptr, nullptr, qkv16, 3 * D, D, 0);

        // fused causal attention -> o16 fp16
        flash_attn_kernel<<<dim3(T / 64, BATCH * H), 128>>>(qkv16, o16);

        // output projection + residual (BM=64: 256 CTAs)
        gemm64_kernel<<<dim3(D / 128, MROWS / 64), 128, GEMM_SMEM_64>>>(
            o16, w16 + OFF_PROJ + (size_t)l * D * D,
            bproj + l * D, h_, h_, nullptr, D, D, 0);

        // MLP
        layernorm_kernel<<<MROWS, 256>>>(h_, ln2_g + l * D, ln2_b + l * D, a16);
        gemm128_kernel<<<dim3(DF / 128, MROWS / 128), 256, GEMM_SMEM_128>>>(
            a16, w16 + OFF_W1 + (size_t)l * D * DF,
            b1 + l * DF, nullptr, nullptr, f16, DF, D, 1);
        gemm64_kernel<<<dim3(D / 128, MROWS / 64), 128, GEMM_SMEM_64>>>(
            f16, w16 + OFF_W2 + (size_t)l * DF * D,
            b2 + l * D, h_, h_, nullptr, D, DF, 0);
    }

    // Final LN + LM head (fp32 out)
    layernorm_kernel<<<MROWS, 256>>>(h_, lnf_g, lnf_b, a16);
    gemm128_kernel<<<dim3(VOCAB / 128, MROWS / 128), 256, GEMM_SMEM_128>>>(
        a16, w16 + OFF_LM, blm, nullptr, out, nullptr, VOCAB, D, 0);
}

// round 16
// speedup vs baseline: 1.4963x; 1.4963x over previous
#include <cuda_runtime.h>
#include <cuda_fp16.h>
#include <cstdint>

// ---------------------------------------------------------------------------
// PoetryGPT forward: fp16 HMMA GEMMs (fp16 weight arena, 3-stage cp.async,
// BN=128 and BN=64 variants) + fused flash attention.
// B=2,T=1024,D=1024,H=16,HD=64,L=8,V=32000,DF=4096
// ---------------------------------------------------------------------------

namespace {
constexpr int BATCH = 2;
constexpr int T     = 1024;
constexpr int D     = 1024;
constexpr int H     = 16;
constexpr int HD    = 64;
constexpr int NL    = 8;
constexpr int VOCAB = 32000;
constexpr int DF    = 4096;
constexpr int MROWS = BATCH * T;      // 2048

// fp16 weight arena, tensor-major, all [K,N] row-major
constexpr size_t QKV_L   = (size_t)D * 3 * D;
constexpr size_t OFF_QKV = 0;
constexpr size_t OFF_PROJ = (size_t)NL * QKV_L;
constexpr size_t OFF_W1   = OFF_PROJ + (size_t)NL * D * D;
constexpr size_t OFF_W2   = OFF_W1 + (size_t)NL * D * DF;
constexpr size_t OFF_LM   = OFF_W2 + (size_t)NL * DF * D;
constexpr size_t W_TOTAL  = OFF_LM + (size_t)D * VOCAB;

// GEMM smem geometry (3-stage)
constexpr int SA_STRIDE = 40;
constexpr int SA_STAGE  = 128 * SA_STRIDE;             // 5120 halfs
constexpr int SB_STRIDE128 = 136;
constexpr int SB_STAGE128  = 32 * SB_STRIDE128;        // 4352 halfs
constexpr int SB_STRIDE64  = 72;
constexpr int SB_STAGE64   = 32 * SB_STRIDE64;         // 2304 halfs
constexpr int GEMM_SMEM_128 = (3 * SA_STAGE + 3 * SB_STAGE128) * 2;  // 56832
constexpr int GEMM_SMEM_64  = (3 * SA_STAGE + 3 * SB_STAGE64) * 2;   // 44544
}

// Scratch (static device globals; no allocation anywhere)
__device__ float  g_h    [MROWS * D];
__device__ __half g_a16  [(size_t)MROWS * D];
__device__ __half g_qkv16[(size_t)MROWS * 3 * D];
__device__ __half g_f16  [(size_t)MROWS * DF];
__device__ __half g_o16  [(size_t)MROWS * D];
__device__ __half g_w16  [W_TOTAL];

// ---------------------------------------------------------------------------
__device__ __forceinline__ uint32_t smem_u32(const void* p) {
    uint32_t a;
    asm("{ .reg .u64 t; cvta.to.shared.u64 t, %1; cvt.u32.u64 %0, t; }"
        : "=r"(a) : "l"(p));
    return a;
}
#define CP_ASYNC16(sa, gp) \
    asm volatile("cp.async.cg.shared.global [%0], [%1], 16;" :: "r"(sa), "l"(gp))
#define CP_COMMIT() asm volatile("cp.async.commit_group;" ::: "memory")

__device__ __forceinline__ void ldmatrix_x4(uint32_t& r0, uint32_t& r1,
                                            uint32_t& r2, uint32_t& r3,
                                            uint32_t addr) {
    asm volatile("ldmatrix.sync.aligned.m8n8.x4.shared.b16 {%0,%1,%2,%3}, [%4];"
                 : "=r"(r0), "=r"(r1), "=r"(r2), "=r"(r3) : "r"(addr));
}
__device__ __forceinline__ void ldmatrix_x4_trans(uint32_t& r0, uint32_t& r1,
                                                  uint32_t& r2, uint32_t& r3,
                                                  uint32_t addr) {
    asm volatile("ldmatrix.sync.aligned.m8n8.x4.trans.shared.b16 {%0,%1,%2,%3}, [%4];"
                 : "=r"(r0), "=r"(r1), "=r"(r2), "=r"(r3) : "r"(addr));
}
__device__ __forceinline__ void mma16816(float* c, const uint32_t* a,
                                         const uint32_t* b) {
    asm volatile(
        "mma.sync.aligned.m16n8k16.row.col.f32.f16.f16.f32 "
        "{%0,%1,%2,%3}, {%4,%5,%6,%7}, {%8,%9}, {%0,%1,%2,%3};"
        : "+f"(c[0]), "+f"(c[1]), "+f"(c[2]), "+f"(c[3])
        : "r"(a[0]), "r"(a[1]), "r"(a[2]), "r"(a[3]), "r"(b[0]), "r"(b[1]));
}
__device__ __forceinline__ uint32_t h2pack(float x, float y) {
    __half2 h = __floats2half2_rn(x, y);
    return *(uint32_t*)&h;
}

// ---------------------------------------------------------------------------
// Block reductions (blockDim.x == 256)
// ---------------------------------------------------------------------------
__device__ __forceinline__ float blk_sum(float v) {
    __shared__ float sm[8];
    int lane = threadIdx.x & 31, w = threadIdx.x >> 5;
    #pragma unroll
    for (int o = 16; o; o >>= 1) v += __shfl_xor_sync(0xffffffffu, v, o);
    if (lane == 0) sm[w] = v;
    __syncthreads();
    if (w == 0) {
        float x = (lane < 8) ? sm[lane] : 0.f;
        #pragma unroll
        for (int o = 4; o; o >>= 1) x += __shfl_xor_sync(0xffffffffu, x, o);
        if (lane == 0) sm[0] = x;
    }
    __syncthreads();
    float r = sm[0];
    __syncthreads();
    return r;
}

// ---------------------------------------------------------------------------
// Weight conversion fp32 -> fp16 (elementwise, layout preserved)
// ---------------------------------------------------------------------------
__global__ void conv_w_kernel(const float* __restrict__ src, __half* __restrict__ dst) {
    size_t i = ((size_t)blockIdx.x * 256 + threadIdx.x) * 8;
    float4 v0 = *(const float4*)(src + i);
    float4 v1 = *(const float4*)(src + i + 4);
    uint2 p0, p1;
    p0.x = h2pack(v0.x, v0.y); p0.y = h2pack(v0.z, v0.w);
    p1.x = h2pack(v1.x, v1.y); p1.y = h2pack(v1.z, v1.w);
    *(uint2*)(dst + i)     = p0;
    *(uint2*)(dst + i + 4) = p1;
}

// ---------------------------------------------------------------------------
// QKV remap + convert: (L,H,D,HD)x3 fp32 -> arena [L][K=D][N=3D] fp16
// ---------------------------------------------------------------------------
__global__ void conv_qkv_kernel(const float* __restrict__ Wq,
                                const float* __restrict__ Wk,
                                const float* __restrict__ Wv,
                                __half* __restrict__ dst) {
    size_t i = ((size_t)blockIdx.x * 256 + threadIdx.x) * 4;
    int l = (int)(i / QKV_L);
    size_t rem = i % QKV_L;
    int k = (int)(rem / (3 * D));
    int col = (int)(rem % (3 * D));
    int s = col >> 10, nloc = col & 1023;
    int h = nloc >> 6, e = nloc & 63;
    const float* base = (s == 0) ? Wq : ((s == 1) ? Wk : Wv);
    const float* src = base + (size_t)l * H * D * HD + ((size_t)h * D + k) * HD + e;
    float4 v = *(const float4*)src;
    uint2 p;
    p.x = h2pack(v.x, v.y);
    p.y = h2pack(v.z, v.w);
    *(uint2*)(dst + i) = p;
}

// ---------------------------------------------------------------------------
// Embedding
// ---------------------------------------------------------------------------
__global__ void embed_kernel(const int* __restrict__ x,
                             const float* __restrict__ tok,
                             const float* __restrict__ pos,
                             float* __restrict__ out) {
    int row = blockIdx.x;
    int t   = row & (T - 1);
    int id  = x[row];
    int c   = threadIdx.x * 4;
    float4 a = *(const float4*)(tok + (size_t)id * D + c);
    float4 p = *(const float4*)(pos + (size_t)t * D + c);
    float4 r; r.x = a.x + p.x; r.y = a.y + p.y; r.z = a.z + p.z; r.w = a.w + p.w;
    *(float4*)(out + (size_t)row * D + c) = r;
}

// ---------------------------------------------------------------------------
// LayerNorm over D=1024, fp32 in -> fp16 out
// ---------------------------------------------------------------------------
__global__ void layernorm_kernel(const float* __restrict__ x,
                                 const float* __restrict__ g,
                                 const float* __restrict__ b,
                                 __half* __restrict__ y) {
    int row = blockIdx.x;
    int c   = threadIdx.x * 4;
    float4 v = *(const float4*)(x + (size_t)row * D + c);
    float mean = blk_sum(v.x + v.y + v.z + v.w) * (1.f / D);
    float dx = v.x - mean, dy = v.y - mean, dz = v.z - mean, dw = v.w - mean;
    float var = blk_sum(dx * dx + dy * dy + dz * dz + dw * dw) * (1.f / D);
    float inv = rsqrtf(var + 1e-5f);
    float4 gv = *(const float4*)(g + c);
    float4 bv = *(const float4*)(b + c);
    __half2* o = (__half2*)(y + (size_t)row * D + c);
    o[0] = __floats2half2_rn(dx * inv * gv.x + bv.x, dy * inv * gv.y + bv.y);
    o[1] = __floats2half2_rn(dz * inv * gv.z + bv.z, dw * inv * gv.w + bv.w);
}

// ---------------------------------------------------------------------------
// HMMA GEMM, BM=128/BN=128: 256 threads (8 warps 4x2), 3-stage cp.async
// (identical to R11 best)
// ---------------------------------------------------------------------------
__global__ void __launch_bounds__(256, 2)
gemm128_kernel(const __half* __restrict__ A, const __half* __restrict__ B,
               const float* __restrict__ bias, const float* res,
               float* __restrict__ Cf, __half* __restrict__ Ch,
               int N, int K, int relu) {
    extern __shared__ __half smem[];
    __half* sA = smem;
    __half* sB = smem + 3 * SA_STAGE;

    int tid = threadIdx.x, lane = tid & 31, wid = tid >> 5;
    int wm = wid & 3, wn = wid >> 2;
    size_t m0 = (size_t)blockIdx.y * 128, n0 = (size_t)blockIdx.x * 128;

    int lr  = tid >> 2;
    int seg = (tid & 3) * 8;
    const __half* Ag0 = A + (m0 + lr) * (size_t)K + seg;
    const __half* Ag1 = A + (m0 + lr + 64) * (size_t)K + seg;
    uint32_t saw0 = smem_u32(sA + lr * SA_STRIDE + seg);
    uint32_t saw1 = smem_u32(sA + (lr + 64) * SA_STRIDE + seg);

    int brow = tid >> 4;
    int bcol = (tid & 15) * 8;
    const __half* Bg = B + (size_t)brow * N + n0 + bcol;
    uint32_t sbw0 = smem_u32(sB + brow * SB_STRIDE128 + bcol);
    uint32_t sbw1 = smem_u32(sB + (brow + 16) * SB_STRIDE128 + bcol);

    int nk = K >> 5;
    auto issue = [&](int kb) {
        uint32_t ao = (uint32_t)((kb % 3) * SA_STAGE * 2);
        uint32_t bo = (uint32_t)((kb % 3) * SB_STAGE128 * 2);
        size_t ga = (size_t)kb * 32;
        CP_ASYNC16(saw0 + ao, Ag0 + ga);
        CP_ASYNC16(saw1 + ao, Ag1 + ga);
        const __half* bg = Bg + (size_t)kb * 32 * N;
        CP_ASYNC16(sbw0 + bo, bg);
        CP_ASYNC16(sbw1 + bo, bg + (size_t)16 * N);
        CP_COMMIT();
    };

    float acc[2][8][4] = {};
    issue(0);
    issue(1);

    for (int kb = 0; kb < nk; kb++) {
        if (kb + 1 < nk) {
            asm volatile("cp.async.wait_group 1;" ::: "memory");
        } else {
            asm volatile("cp.async.wait_group 0;" ::: "memory");
        }
        __syncthreads();
        if (kb + 2 < nk) issue(kb + 2);

        const __half* bufA = sA + (kb % 3) * SA_STAGE;
        const __half* bufB = sB + (kb % 3) * SB_STAGE128;
        #pragma unroll
        for (int ks = 0; ks < 2; ks++) {
            uint32_t a[2][4], b[8][2];
            #pragma unroll
            for (int mt = 0; mt < 2; mt++) {
                uint32_t ad = smem_u32(
                    bufA + (wm * 32 + mt * 16 + (lane & 15)) * SA_STRIDE +
                    ks * 16 + (lane >> 4) * 8);
                ldmatrix_x4(a[mt][0], a[mt][1], a[mt][2], a[mt][3], ad);
            }
            #pragma unroll
            for (int j2 = 0; j2 < 4; j2++) {
                uint32_t r0, r1, r2, r3;
                uint32_t bd = smem_u32(
                    bufB + (ks * 16 + (lane & 15)) * SB_STRIDE128 +
                    wn * 64 + j2 * 16 + (lane >> 4) * 8);
                ldmatrix_x4_trans(r0, r1, r2, r3, bd);
                b[j2 * 2][0] = r0; b[j2 * 2][1] = r1;
                b[j2 * 2 + 1][0] = r2; b[j2 * 2 + 1][1] = r3;
            }
            #pragma unroll
            for (int mt = 0; mt < 2; mt++)
                #pragma unroll
                for (int nt = 0; nt < 8; nt++)
                    mma16816(acc[mt][nt], a[mt], b[nt]);
        }
    }

    int rg = lane >> 2, cg = (lane & 3) * 2;
    #pragma unroll
    for (int mt = 0; mt < 2; mt++) {
        #pragma unroll
        for (int half = 0; half < 2; half++) {
            size_t r = m0 + wm * 32 + mt * 16 + rg + half * 8;
            #pragma unroll
            for (int nt = 0; nt < 8; nt++) {
                size_t c = n0 + wn * 64 + nt * 8 + cg;
                float vx = acc[mt][nt][half * 2 + 0];
                float vy = acc[mt][nt][half * 2 + 1];
                if (bias) { vx += bias[c]; vy += bias[c + 1]; }
                if (res) {
                    float2 rv = *(const float2*)(res + r * N + c);
                    vx += rv.x; vy += rv.y;
                }
                if (relu) { vx = fmaxf(vx, 0.f); vy = fmaxf(vy, 0.f); }
                if (Ch) {
                    *(__half2*)(Ch + r * N + c) = __floats2half2_rn(vx, vy);
                } else {
                    float2 v; v.x = vx; v.y = vy;
                    *(float2*)(Cf + r * N + c) = v;
                }
            }
        }
    }
}

// ---------------------------------------------------------------------------
// HMMA GEMM, BM=128/BN=64: 256 threads (8 warps 4x2, warp tile 32x32),
// 3-stage cp.async. For proj/W2 (N=1024): grid (16,16)=256 CTAs.
// ---------------------------------------------------------------------------
__global__ void __launch_bounds__(256, 2)
gemmN64_kernel(const __half* __restrict__ A, const __half* __restrict__ B,
               const float* __restrict__ bias, const float* res,
               float* __restrict__ Cf, __half* __restrict__ Ch,
               int N, int K, int relu) {
    extern __shared__ __half smem[];
    __half* sA = smem;
    __half* sB = smem + 3 * SA_STAGE;

    int tid = threadIdx.x, lane = tid & 31, wid = tid >> 5;
    int wm = wid & 3, wn = wid >> 2;   // wn in {0,1}: cols wn*32..+31
    size_t m0 = (size_t)blockIdx.y * 128, n0 = (size_t)blockIdx.x * 64;

    int lr  = tid >> 2;
    int seg = (tid & 3) * 8;
    const __half* Ag0 = A + (m0 + lr) * (size_t)K + seg;
    const __half* Ag1 = A + (m0 + lr + 64) * (size_t)K + seg;
    uint32_t saw0 = smem_u32(sA + lr * SA_STRIDE + seg);
    uint32_t saw1 = smem_u32(sA + (lr + 64) * SA_STRIDE + seg);

    // B: 32x64 per stage = 256 x 16B chunks, 1 per thread
    int brow = tid >> 3;            // 0..31
    int bcol = (tid & 7) * 8;       // 0..56
    const __half* Bg = B + (size_t)brow * N + n0 + bcol;
    uint32_t sbw = smem_u32(sB + brow * SB_STRIDE64 + bcol);

    int nk = K >> 5;
    auto issue = [&](int kb) {
        uint32_t ao = (uint32_t)((kb % 3) * SA_STAGE * 2);
        uint32_t bo = (uint32_t)((kb % 3) * SB_STAGE64 * 2);
        size_t ga = (size_t)kb * 32;
        CP_ASYNC16(saw0 + ao, Ag0 + ga);
        CP_ASYNC16(saw1 + ao, Ag1 + ga);
        CP_ASYNC16(sbw + bo, Bg + (size_t)kb * 32 * N);
        CP_COMMIT();
    };

    float acc[2][4][4] = {};
    issue(0);
    issue(1);

    for (int kb = 0; kb < nk; kb++) {
        if (kb + 1 < nk) {
            asm volatile("cp.async.wait_group 1;" ::: "memory");
        } else {
            asm volatile("cp.async.wait_group 0;" ::: "memory");
        }
        __syncthreads();
        if (kb + 2 < nk) issue(kb + 2);

        const __half* bufA = sA + (kb % 3) * SA_STAGE;
        const __half* bufB = sB + (kb % 3) * SB_STAGE64;
        #pragma unroll
        for (int ks = 0; ks < 2; ks++) {
            uint32_t a[2][4], b[4][2];
            #pragma unroll
            for (int mt = 0; mt < 2; mt++) {
                uint32_t ad = smem_u32(
                    bufA + (wm * 32 + mt * 16 + (lane & 15)) * SA_STRIDE +
                    ks * 16 + (lane >> 4) * 8);
                ldmatrix_x4(a[mt][0], a[mt][1], a[mt][2], a[mt][3], ad);
            }
            #pragma unroll
            for (int j2 = 0; j2 < 2; j2++) {
                uint32_t r0, r1, r2, r3;
                uint32_t bd = smem_u32(
                    bufB + (ks * 16 + (lane & 15)) * SB_STRIDE64 +
                    wn * 32 + j2 * 16 + (lane >> 4) * 8);
                ldmatrix_x4_trans(r0, r1, r2, r3, bd);
                b[j2 * 2][0] = r0; b[j2 * 2][1] = r1;
                b[j2 * 2 + 1][0] = r2; b[j2 * 2 + 1][1] = r3;
            }
            #pragma unroll
            for (int mt = 0; mt < 2; mt++)
                #pragma unroll
                for (int nt = 0; nt < 4; nt++)
                    mma16816(acc[mt][nt], a[mt], b[nt]);
        }
    }

    int rg = lane >> 2, cg = (lane & 3) * 2;
    #pragma unroll
    for (int mt = 0; mt < 2; mt++) {
        #pragma unroll
        for (int half = 0; half < 2; half++) {
            size_t r = m0 + wm * 32 + mt * 16 + rg + half * 8;
            #pragma unroll
            for (int nt = 0; nt < 4; nt++) {
                size_t c = n0 + wn * 32 + nt * 8 + cg;
                float vx = acc[mt][nt][half * 2 + 0];
                float vy = acc[mt][nt][half * 2 + 1];
                if (bias) { vx += bias[c]; vy += bias[c + 1]; }
                if (res) {
                    float2 rv = *(const float2*)(res + r * N + c);
                    vx += rv.x; vy += rv.y;
                }
                if (relu) { vx = fmaxf(vx, 0.f); vy = fmaxf(vy, 0.f); }
                if (Ch) {
                    *(__half2*)(Ch + r * N + c) = __floats2half2_rn(vx, vy);
                } else {
                    float2 v; v.x = vx; v.y = vy;
                    *(float2*)(Cf + r * N + c) = v;
                }
            }
        }
    }
}

// ---------------------------------------------------------------------------
// Fused causal flash attention (fp16 HMMA, fp32 online softmax)
// ---------------------------------------------------------------------------
__global__ void __launch_bounds__(128)
flash_attn_kernel(const __half* __restrict__ qkv, __half* __restrict__ o16) {
    constexpr int RS = 3 * D;
    constexpr int ST = 72;
    __shared__ __half sQ[64 * ST];
    __shared__ __half sK[2][64 * ST];
    __shared__ __half sV[2][64 * ST];

    int tid = threadIdx.x, lane = tid & 31, wid = tid >> 5;
    int bh = blockIdx.y;
    int b = bh >> 4, h = bh & 15;
    int tt = gridDim.x - 1 - blockIdx.x;
    int t0 = tt * 64;

    const __half* qb = qkv + (size_t)(b * T) * RS + h * HD;
    const __half* kb = qb + D;
    const __half* vb = qb + 2 * D;

    int seg = (tid & 7) * 8, rr = tid >> 3;
    #pragma unroll
    for (int i = 0; i < 4; i++) {
        int row = rr + i * 16;
        *(uint4*)&sQ[row * ST + seg] =
            *(const uint4*)(qb + (size_t)(t0 + row) * RS + seg);
    }
    __syncthreads();

    uint32_t qa[4][4];
    {
        int qr = wid * 16 + (lane & 15);
        #pragma unroll
        for (int kk = 0; kk < 4; kk++) {
            uint32_t ad = smem_u32(&sQ[qr * ST + kk * 16 + (lane >> 4) * 8]);
            ldmatrix_x4(qa[kk][0], qa[kk][1], qa[kk][2], qa[kk][3], ad);
        }
    }

    float m[2] = {-1e30f, -1e30f}, l[2] = {0.f, 0.f};
    float oacc[8][4] = {};
    int nst = tt + 1;

    {
        #pragma unroll
        for (int i = 0; i < 4; i++) {
            int row = rr + i * 16;
            CP_ASYNC16(smem_u32(&sK[0][row * ST + seg]), kb + (size_t)row * RS + seg);
            CP_ASYNC16(smem_u32(&sV[0][row * ST + seg]), vb + (size_t)row * RS + seg);
        }
        CP_COMMIT();
    }

    const float scale = 0.03125f;
    int trow0 = t0 + wid * 16 + (lane >> 2);

    for (int st = 0; st < nst; st++) {
        int buf = st & 1;
        asm volatile("cp.async.wait_group 0;" ::: "memory");
        __syncthreads();
        if (st + 1 < nst) {
            int nb = buf ^ 1;
            #pragma unroll
            for (int i = 0; i < 4; i++) {
                int row = rr + i * 16;
                const __half* kg = kb + (size_t)((st + 1) * 64 + row) * RS + seg;
                const __half* vg = vb + (size_t)((st + 1) * 64 + row) * RS + seg;
                CP_ASYNC16(smem_u32(&sK[nb][row * ST + seg]), kg);
                CP_ASYNC16(smem_u32(&sV[nb][row * ST + seg]), vg);
            }
            CP_COMMIT();
        }

        float sacc[8][4] = {};
        #pragma unroll
        for (int kk = 0; kk < 4; kk++) {
            uint32_t bfr[8][2];
            #pragma unroll
            for (int j2 = 0; j2 < 4; j2++) {
                uint32_t r0, r1, r2, r3;
                uint32_t ad = smem_u32(
                    &sK[buf][(j2 * 16 + (lane & 15)) * ST + kk * 16 + (lane >> 4) * 8]);
                ldmatrix_x4(r0, r1, r2, r3, ad);
                bfr[j2 * 2][0] = r0; bfr[j2 * 2][1] = r2;
                bfr[j2 * 2 + 1][0] = r1; bfr[j2 * 2 + 1][1] = r3;
            }
            #pragma unroll
            for (int j = 0; j < 8; j++)
                mma16816(sacc[j], qa[kk], bfr[j]);
        }

        bool diag = (st == tt);
        #pragma unroll
        for (int j = 0; j < 8; j++) {
            #pragma unroll
            for (int q = 0; q < 4; q++) {
                float v = sacc[j][q] * scale;
                if (diag) {
                    int s = st * 64 + j * 8 + (lane & 3) * 2 + (q & 1);
                    int t = trow0 + ((q < 2) ? 0 : 8);
                    if (s > t) v = -1e30f;
                }
                sacc[j][q] = v;
            }
        }

        float mx0 = -1e30f, mx1 = -1e30f;
        #pragma unroll
        for (int j = 0; j < 8; j++) {
            mx0 = fmaxf(mx0, fmaxf(sacc[j][0], sacc[j][1]));
            mx1 = fmaxf(mx1, fmaxf(sacc[j][2], sacc[j][3]));
        }
        #pragma unroll
        for (int o = 1; o <= 2; o <<= 1) {
            mx0 = fmaxf(mx0, __shfl_xor_sync(0xffffffffu, mx0, o));
            mx1 = fmaxf(mx1, __shfl_xor_sync(0xffffffffu, mx1, o));
        }
        float mn0 = fmaxf(m[0], mx0), mn1 = fmaxf(m[1], mx1);
        float a0 = __expf(m[0] - mn0), a1 = __expf(m[1] - mn1);
        m[0] = mn0; m[1] = mn1;

        float s0 = 0.f, s1 = 0.f;
        #pragma unroll
        for (int j = 0; j < 8; j++) {
            sacc[j][0] = __expf(sacc[j][0] - mn0);
            sacc[j][1] = __expf(sacc[j][1] - mn0);
            sacc[j][2] = __expf(sacc[j][2] - mn1);
            sacc[j][3] = __expf(sacc[j][3] - mn1);
            s0 += sacc[j][0] + sacc[j][1];
            s1 += sacc[j][2] + sacc[j][3];
        }
        #pragma unroll
        for (int o = 1; o <= 2; o <<= 1) {
            s0 += __shfl_xor_sync(0xffffffffu, s0, o);
            s1 += __shfl_xor_sync(0xffffffffu, s1, o);
        }
        l[0] = l[0] * a0 + s0;
        l[1] = l[1] * a1 + s1;
        #pragma unroll
        for (int j = 0; j < 8; j++) {
            oacc[j][0] *= a0; oacc[j][1] *= a0;
            oacc[j][2] *= a1; oacc[j][3] *= a1;
        }

        #pragma unroll
        for (int kk = 0; kk < 4; kk++) {
            uint32_t pa[4];
            pa[0] = h2pack(sacc[2 * kk][0], sacc[2 * kk][1]);
            pa[1] = h2pack(sacc[2 * kk][2], sacc[2 * kk][3]);
            pa[2] = h2pack(sacc[2 * kk + 1][0], sacc[2 * kk + 1][1]);
            pa[3] = h2pack(sacc[2 * kk + 1][2], sacc[2 * kk + 1][3]);
            uint32_t vfr[8][2];
            #pragma unroll
            for (int j2 = 0; j2 < 4; j2++) {
                uint32_t r0, r1, r2, r3;
                uint32_t ad = smem_u32(
                    &sV[buf][(kk * 16 + (lane & 15)) * ST + j2 * 16 + (lane >> 4) * 8]);
                ldmatrix_x4_trans(r0, r1, r2, r3, ad);
                vfr[j2 * 2][0] = r0; vfr[j2 * 2][1] = r1;
                vfr[j2 * 2 + 1][0] = r2; vfr[j2 * 2 + 1][1] = r3;
            }
            #pragma unroll
            for (int j = 0; j < 8; j++)
                mma16816(oacc[j], pa, vfr[j]);
        }
    }

    float inv0 = 1.f / l[0], inv1 = 1.f / l[1];
    int cg = (lane & 3) * 2;
    #pragma unroll
    for (int j = 0; j < 8; j++) {
        size_t r0 = (size_t)(b * T + trow0);
        size_t r1 = r0 + 8;
        int c = h * HD + j * 8 + cg;
        *(__half2*)(o16 + r0 * D + c) = __floats2half2_rn(oacc[j][0] * inv0, oacc[j][1] * inv0);
        *(__half2*)(o16 + r1 * D + c) = __floats2half2_rn(oacc[j][2] * inv1, oacc[j][3] * inv1);
    }
}

// ---------------------------------------------------------------------------
// Host orchestration
// ---------------------------------------------------------------------------
extern "C" void kernel_launch(void* const* d_in, const int* in_sizes, int n_in,
                              void* d_out, int out_size) {
    (void)in_sizes; (void)n_in; (void)out_size;
    const int*   x      = (const int*)  d_in[0];
    const float* tok    = (const float*)d_in[1];
    const float* pos    = (const float*)d_in[2];
    const float* Wq     = (const float*)d_in[3];
    const float* Wk     = (const float*)d_in[4];
    const float* Wv     = (const float*)d_in[5];
    const float* Wproj  = (const float*)d_in[6];
    const float* bproj  = (const float*)d_in[7];
    const float* ln1_g  = (const float*)d_in[8];
    const float* ln1_b  = (const float*)d_in[9];
    const float* ln2_g  = (const float*)d_in[10];
    const float* ln2_b  = (const float*)d_in[11];
    const float* W1     = (const float*)d_in[12];
    const float* b1     = (const float*)d_in[13];
    const float* W2     = (const float*)d_in[14];
    const float* b2     = (const float*)d_in[15];
    const float* lnf_g  = (const float*)d_in[16];
    const float* lnf_b  = (const float*)d_in[17];
    const float* Wlm    = (const float*)d_in[18];
    const float* blm    = (const float*)d_in[19];
    float* out = (float*)d_out;

    float *h_;
    __half *a16, *qkv16, *f16, *o16, *w16;
    cudaGetSymbolAddress((void**)&h_,    g_h);
    cudaGetSymbolAddress((void**)&a16,   g_a16);
    cudaGetSymbolAddress((void**)&qkv16, g_qkv16);
    cudaGetSymbolAddress((void**)&f16,   g_f16);
    cudaGetSymbolAddress((void**)&o16,   g_o16);
    cudaGetSymbolAddress((void**)&w16,   g_w16);

    static int smem_set = 0;
    if (!smem_set) {
        cudaFuncSetAttribute(gemm128_kernel,
                             cudaFuncAttributeMaxDynamicSharedMemorySize, GEMM_SMEM_128);
        cudaFuncSetAttribute(gemmN64_kernel,
                             cudaFuncAttributeMaxDynamicSharedMemorySize, GEMM_SMEM_64);
        smem_set = 1;
    }

    // ---- weight conversion fp32 -> fp16 arena (5 launches) ----
    conv_qkv_kernel<<<(unsigned)(NL * QKV_L / 1024), 256>>>(Wq, Wk, Wv, w16 + OFF_QKV);
    conv_w_kernel<<<(unsigned)((size_t)NL * D * D / 2048), 256>>>(Wproj, w16 + OFF_PROJ);
    conv_w_kernel<<<(unsigned)((size_t)NL * D * DF / 2048), 256>>>(W1, w16 + OFF_W1);
    conv_w_kernel<<<(unsigned)((size_t)NL * DF * D / 2048), 256>>>(W2, w16 + OFF_W2);
    conv_w_kernel<<<(unsigned)((size_t)D * VOCAB / 2048), 256>>>(Wlm, w16 + OFF_LM);

    embed_kernel<<<MROWS, 256>>>(x, tok, pos, h_);

    for (int l = 0; l < NL; l++) {
        layernorm_kernel<<<MROWS, 256>>>(h_, ln1_g + l * D, ln1_b + l * D, a16);

        // fused QKV GEMM (384 CTAs, BN=128)
        gemm128_kernel<<<dim3(3 * D / 128, MROWS / 128), 256, GEMM_SMEM_128>>>(
            a16, w16 + OFF_QKV + (size_t)l * QKV_L,
            nullptr, nullptr, nullptr, qkv16, 3 * D, D, 0);

        // fused causal attention -> o16 fp16
        flash_attn_kernel<<<dim3(T / 64, BATCH * H), 128>>>(qkv16, o16);

        // output projection + residual (BN=64: 256 CTAs)
        gemmN64_kernel<<<dim3(D / 64, MROWS / 128), 256, GEMM_SMEM_64>>>(
            o16, w16 + OFF_PROJ + (size_t)l * D * D,
            bproj + l * D, h_, h_, nullptr, D, D, 0);

        // MLP
        layernorm_kernel<<<MROWS, 256>>>(h_, ln2_g + l * D, ln2_b + l * D, a16);
        gemm128_kernel<<<dim3(DF / 128, MROWS / 128), 256, GEMM_SMEM_128>>>(
            a16, w16 + OFF_W1 + (size_t)l * D * DF,
            b1 + l * DF, nullptr, nullptr, f16, DF, D, 1);
        gemmN64_kernel<<<dim3(D / 64, MROWS / 128), 256, GEMM_SMEM_64>>>(
            f16, w16 + OFF_W2 + (size_t)l * DF * D,
            b2 + l * D, h_, h_, nullptr, D, DF, 0);
    }

    // Final LN + LM head (fp32 out)
    layernorm_kernel<<<MROWS, 256>>>(h_, lnf_g, lnf_b, a16);
    gemm128_kernel<<<dim3(VOCAB / 128, MROWS / 128), 256, GEMM_SMEM_128>>>(
        a16, w16 + OFF_LM, blm, nullptr, out, nullptr, VOCAB, D, 0);
}